// round 8
// baseline (speedup 1.0000x reference)
#include <cuda_runtime.h>
#include <stdint.h>

#define NH   8
#define HD   64
#define NTOK 4096
#define EMB  512
#define CIN  512

// Scratch Q/K/V in [b][h][n][d] layout, values pre-rounded to tf32.
// Q additionally pre-scaled by 0.125 * log2(e).
__device__ float g_Q[2*NH*NTOK*HD];
__device__ float g_K[2*NH*NTOK*HD];
__device__ float g_V[2*NH*NTOK*HD];

// ---------------------------------------------------------------------------
__device__ __forceinline__ uint32_t f2tf(float x){
    uint32_t u; asm("cvt.rna.tf32.f32 %0, %1;" : "=r"(u) : "f"(x)); return u;
}
__device__ __forceinline__ float ex2f(float x){
    float r; asm("ex2.approx.ftz.f32 %0, %1;" : "=f"(r) : "f"(x)); return r;
}
__device__ __forceinline__ uint32_t smem_u32(const void* p) {
    uint32_t a;
    asm("{ .reg .u64 t; cvta.to.shared.u64 t, %1; cvt.u32.u64 %0, t; }" : "=r"(a) : "l"(p));
    return a;
}
__device__ __forceinline__ void mma8(float* c, const uint32_t* a, uint32_t b0, uint32_t b1){
    asm volatile("mma.sync.aligned.m16n8k8.row.col.f32.tf32.tf32.f32 "
        "{%0,%1,%2,%3},{%4,%5,%6,%7},{%8,%9},{%0,%1,%2,%3};"
        : "+f"(c[0]),"+f"(c[1]),"+f"(c[2]),"+f"(c[3])
        : "r"(a[0]),"r"(a[1]),"r"(a[2]),"r"(a[3]),"r"(b0),"r"(b1));
}
#define CP16(dst, src) asm volatile("cp.async.cg.shared.global [%0], [%1], 16;" :: "r"(dst), "l"(src) : "memory")
#define CP_COMMIT()    asm volatile("cp.async.commit_group;" ::: "memory")
#define CP_WAIT0()     asm volatile("cp.async.wait_group 0;" ::: "memory")
#define CP_WAIT1()     asm volatile("cp.async.wait_group 1;" ::: "memory")

// ---------------------------------------------------------------------------
// Projection (tf32 mma): O[b][h][n][d] = X_tok @ W^T + bias
// Epilogue rounds to tf32 (Q pre-scaled) so attention can cp.async raw bytes.
// ---------------------------------------------------------------------------
__global__ __launch_bounds__(256, 2) void proj_mma(
    const float* __restrict__ query, const float* __restrict__ key,
    const float* __restrict__ Wq, const float* __restrict__ bq,
    const float* __restrict__ Wk, const float* __restrict__ bk,
    const float* __restrict__ Wv, const float* __restrict__ bv)
{
    const int z = blockIdx.z;
    const float* X    = (z == 0) ? query : key;
    const float* W    = (z == 0) ? Wq : (z == 1 ? Wk : Wv);
    const float* bias = (z == 0) ? bq : (z == 1 ? bk : bv);
    float* O          = (z == 0) ? g_Q : (z == 1 ? g_K : g_V);
    const float osc   = (z == 0) ? 0.18033688011112042f : 1.0f;  // 0.125*log2(e)

    const int b  = blockIdx.x >> 5;
    const int n0 = (blockIdx.x & 31) * 128;
    const int e0 = blockIdx.y * 128;

    __shared__ uint32_t Au[16*132];
    __shared__ uint32_t Wu[16*132];

    const int tid = threadIdx.x, lane = tid & 31, w = tid >> 5;
    const int g = lane >> 2, t = lane & 3;
    const int wm = w >> 1, wn = w & 1;

    float acc[2][8][4];
    #pragma unroll
    for (int mb = 0; mb < 2; mb++)
        #pragma unroll
        for (int nb = 0; nb < 8; nb++)
            #pragma unroll
            for (int c = 0; c < 4; c++) acc[mb][nb][c] = 0.f;

    const size_t xbase = (size_t)b * CIN * NTOK;

    for (int c0 = 0; c0 < CIN; c0 += 16) {
        __syncthreads();
        #pragma unroll
        for (int it = 0; it < 2; it++) {
            int i = tid + it*256;
            int c = i >> 5, nq = (i & 31) * 4;
            float4 v = *(const float4*)&X[xbase + (size_t)(c0 + c) * NTOK + n0 + nq];
            uint4 u = { f2tf(v.x), f2tf(v.y), f2tf(v.z), f2tf(v.w) };
            *(uint4*)&Au[c*132 + nq] = u;
        }
        #pragma unroll
        for (int it = 0; it < 2; it++) {
            int i = tid + it*256;
            int e = i >> 2, cq = (i & 3) * 4;
            float4 v = *(const float4*)&W[(size_t)(e0 + e) * CIN + c0 + cq];
            Wu[(cq+0)*132 + e] = f2tf(v.x);
            Wu[(cq+1)*132 + e] = f2tf(v.y);
            Wu[(cq+2)*132 + e] = f2tf(v.z);
            Wu[(cq+3)*132 + e] = f2tf(v.w);
        }
        __syncthreads();

        #pragma unroll
        for (int kc = 0; kc < 2; kc++) {
            uint32_t a[2][4];
            #pragma unroll
            for (int mb = 0; mb < 2; mb++) {
                int r = wm*32 + mb*16;
                a[mb][0] = Au[(kc*8+t  )*132 + r + g];
                a[mb][1] = Au[(kc*8+t  )*132 + r + g + 8];
                a[mb][2] = Au[(kc*8+t+4)*132 + r + g];
                a[mb][3] = Au[(kc*8+t+4)*132 + r + g + 8];
            }
            #pragma unroll
            for (int nb = 0; nb < 8; nb++) {
                int e = wn*64 + nb*8;
                uint32_t b0 = Wu[(kc*8+t  )*132 + e + g];
                uint32_t b1 = Wu[(kc*8+t+4)*132 + e + g];
                mma8(acc[0][nb], a[0], b0, b1);
                mma8(acc[1][nb], a[1], b0, b1);
            }
        }
    }

    #pragma unroll
    for (int mb = 0; mb < 2; mb++) {
        #pragma unroll
        for (int nb = 0; nb < 8; nb++) {
            int e = e0 + wn*64 + nb*8 + 2*t;
            float2 bb = *(const float2*)&bias[e];
            int h = e >> 6, d = e & 63;
            int n = n0 + wm*32 + mb*16 + g;
            float* o0 = &O[(((size_t)b*NH + h)*NTOK + n)*HD + d];
            float2 v0 = { __uint_as_float(f2tf((acc[mb][nb][0] + bb.x) * osc)),
                          __uint_as_float(f2tf((acc[mb][nb][1] + bb.y) * osc)) };
            *(float2*)o0 = v0;
            float2 v1 = { __uint_as_float(f2tf((acc[mb][nb][2] + bb.x) * osc)),
                          __uint_as_float(f2tf((acc[mb][nb][3] + bb.y) * osc)) };
            *(float2*)(o0 + 8*HD) = v1;
        }
    }
}

// ---------------------------------------------------------------------------
// Flash attention (tf32 mma). Paired q-tiles for perfect load balance:
// block `pair` processes qt = 31-pair then qt = pair  (66 key-tiles total).
// 2-stage cp.async K/V pipeline. 8 warps x 16 rows, 128-query tiles.
// ---------------------------------------------------------------------------
#define KSTR 76
#define VSTR 72
#define PSTR 68
#define OSTR 132
#define OFF_K0 0
#define OFF_V0 (64*KSTR)                 // 4864
#define OFF_K1 (OFF_V0 + 64*VSTR)        // 9472
#define OFF_V1 (OFF_K1 + 64*KSTR)        // 14336
#define OFF_P  (OFF_V1 + 64*VSTR)        // 18944
#define SMF    (OFF_P + 128*PSTR)        // 27648 floats = 110,592 B

__device__ __forceinline__ void stage_kv(uint32_t sb, const float* Kg, const float* Vg,
                                         int n0, int kOff, int vOff, int tid)
{
    #pragma unroll
    for (int it = 0; it < 4; it++) {
        int i = tid + it*256, r = i >> 4, c = (i & 15) * 4;
        CP16(sb + (uint32_t)(kOff + r*KSTR + c)*4u, Kg + (size_t)(n0 + r)*HD + c);
    }
    #pragma unroll
    for (int it = 0; it < 4; it++) {
        int i = tid + it*256, r = i >> 4, c = (i & 15) * 4;
        CP16(sb + (uint32_t)(vOff + r*VSTR + c)*4u, Vg + (size_t)(n0 + r)*HD + c);
    }
}

__global__ __launch_bounds__(256, 2) void attn_mma(float* __restrict__ out)
{
    const int pair = blockIdx.x;         // 0..15
    const int h    = blockIdx.y;
    const int b    = blockIdx.z;

    extern __shared__ float sm[];
    uint32_t* smu = (uint32_t*)sm;
    const uint32_t sb = smem_u32(sm);

    const int tid = threadIdx.x, lane = tid & 31, w = tid >> 5;
    const int g = lane >> 2, t = lane & 3;
    const int r0 = w*16 + g;

    const size_t base = ((size_t)(b*NH + h)) * NTOK * HD;
    const float* Kg = g_K + base;
    const float* Vg = g_V + base;

    for (int half = 0; half < 2; half++) {
        const int qt = half ? pair : (31 - pair);
        const int qbase  = qt * 128;
        const int ntiles = 2*qt + 2;

        __syncthreads();   // protect P region / buffers from previous half

        // stage Q (pre-scaled tf32) into P region; stage K/V tile 0 into buf0
        #pragma unroll
        for (int it = 0; it < 8; it++) {
            int i = tid + it*256, r = i >> 4, c = (i & 15) * 4;
            CP16(sb + (uint32_t)(OFF_P + r*PSTR + c)*4u,
                 g_Q + base + (size_t)(qbase + r)*HD + c);
        }
        stage_kv(sb, Kg, Vg, 0, OFF_K0, OFF_V0, tid);
        CP_COMMIT();
        CP_WAIT0();
        __syncthreads();

        // lift Q fragments (held in registers for both tiles of this half)
        uint32_t qf[8][4];
        #pragma unroll
        for (int kc = 0; kc < 8; kc++) {
            qf[kc][0] = smu[OFF_P + ( r0   )*PSTR + kc*8 + t];
            qf[kc][1] = smu[OFF_P + (r0+8 )*PSTR + kc*8 + t];
            qf[kc][2] = smu[OFF_P + ( r0   )*PSTR + kc*8 + t + 4];
            qf[kc][3] = smu[OFF_P + (r0+8 )*PSTR + kc*8 + t + 4];
        }

        float acc[8][4];
        #pragma unroll
        for (int nb = 0; nb < 8; nb++)
            #pragma unroll
            for (int c = 0; c < 4; c++) acc[nb][c] = 0.f;
        float m0 = -1e30f, m1 = -1e30f, l0 = 0.f, l1 = 0.f;

        for (int j = 0; j < ntiles; j++) {
            const int n0 = j * 64;
            const int kb = (j & 1) ? OFF_K1 : OFF_K0;
            const int vb = (j & 1) ? OFF_V1 : OFF_V0;

            if (j + 1 < ntiles) {
                stage_kv(sb, Kg, Vg, (j+1)*64,
                         ((j+1) & 1) ? OFF_K1 : OFF_K0,
                         ((j+1) & 1) ? OFF_V1 : OFF_V0, tid);
                CP_COMMIT();
                CP_WAIT1();
            } else {
                CP_WAIT0();
            }
            __syncthreads();

            // S = Q K^T  (16 rows x 64 keys per warp)
            float s[8][4];
            #pragma unroll
            for (int nb = 0; nb < 8; nb++)
                #pragma unroll
                for (int c = 0; c < 4; c++) s[nb][c] = 0.f;
            #pragma unroll
            for (int kc = 0; kc < 8; kc++)
                #pragma unroll
                for (int nb = 0; nb < 8; nb++) {
                    uint32_t b0 = smu[kb + (nb*8+g)*KSTR + kc*8 + t];
                    uint32_t b1 = smu[kb + (nb*8+g)*KSTR + kc*8 + t + 4];
                    mma8(s[nb], qf[kc], b0, b1);
                }

            if (j >= 2*qt) {   // diagonal tiles: causal mask
                const int row = qbase + r0;
                #pragma unroll
                for (int nb = 0; nb < 8; nb++) {
                    int col = n0 + nb*8 + 2*t;
                    if (col     > row  ) s[nb][0] = -1e30f;
                    if (col + 1 > row  ) s[nb][1] = -1e30f;
                    if (col     > row+8) s[nb][2] = -1e30f;
                    if (col + 1 > row+8) s[nb][3] = -1e30f;
                }
            }

            // online softmax (rows r0 and r0+8), base-2 domain
            float mx0 = -1e30f, mx1 = -1e30f;
            #pragma unroll
            for (int nb = 0; nb < 8; nb++) {
                mx0 = fmaxf(mx0, fmaxf(s[nb][0], s[nb][1]));
                mx1 = fmaxf(mx1, fmaxf(s[nb][2], s[nb][3]));
            }
            mx0 = fmaxf(mx0, __shfl_xor_sync(0xffffffffu, mx0, 1));
            mx0 = fmaxf(mx0, __shfl_xor_sync(0xffffffffu, mx0, 2));
            mx1 = fmaxf(mx1, __shfl_xor_sync(0xffffffffu, mx1, 1));
            mx1 = fmaxf(mx1, __shfl_xor_sync(0xffffffffu, mx1, 2));
            float mn0 = fmaxf(m0, mx0), mn1 = fmaxf(m1, mx1);
            float sc0 = ex2f(m0 - mn0), sc1 = ex2f(m1 - mn1);
            float ps0 = 0.f, ps1 = 0.f;
            uint32_t* pr0 = &smu[OFF_P + ( r0  )*PSTR + 2*t];
            uint32_t* pr1 = &smu[OFF_P + (r0+8)*PSTR + 2*t];
            #pragma unroll
            for (int nb = 0; nb < 8; nb++) {
                float p0 = ex2f(s[nb][0]-mn0), p1 = ex2f(s[nb][1]-mn0);
                float p2 = ex2f(s[nb][2]-mn1), p3 = ex2f(s[nb][3]-mn1);
                ps0 += p0 + p1;  ps1 += p2 + p3;
                acc[nb][0] *= sc0; acc[nb][1] *= sc0;
                acc[nb][2] *= sc1; acc[nb][3] *= sc1;
                pr0[nb*8+0] = f2tf(p0); pr0[nb*8+1] = f2tf(p1);
                pr1[nb*8+0] = f2tf(p2); pr1[nb*8+1] = f2tf(p3);
            }
            ps0 += __shfl_xor_sync(0xffffffffu, ps0, 1);
            ps0 += __shfl_xor_sync(0xffffffffu, ps0, 2);
            ps1 += __shfl_xor_sync(0xffffffffu, ps1, 1);
            ps1 += __shfl_xor_sync(0xffffffffu, ps1, 2);
            l0 = l0*sc0 + ps0;  l1 = l1*sc1 + ps1;
            m0 = mn0;  m1 = mn1;
            __syncwarp();

            // O += P V   (P rows are warp-private)
            #pragma unroll
            for (int kc = 0; kc < 8; kc++) {
                uint32_t pa[4];
                pa[0] = smu[OFF_P + ( r0  )*PSTR + kc*8 + t];
                pa[1] = smu[OFF_P + (r0+8)*PSTR + kc*8 + t];
                pa[2] = smu[OFF_P + ( r0  )*PSTR + kc*8 + t + 4];
                pa[3] = smu[OFF_P + (r0+8)*PSTR + kc*8 + t + 4];
                #pragma unroll
                for (int nb = 0; nb < 8; nb++) {
                    uint32_t b0 = smu[vb + (kc*8+t  )*VSTR + nb*8 + g];
                    uint32_t b1 = smu[vb + (kc*8+t+4)*VSTR + nb*8 + g];
                    mma8(acc[nb], pa, b0, b1);
                }
            }
            __syncthreads();   // all warps done with buf j & P before overwrite
        }

        // finalize: /l, stage transposed in P region, coalesced write out[b][e][n]
        float inv0 = 1.f / l0, inv1 = 1.f / l1;
        #pragma unroll
        for (int nb = 0; nb < 8; nb++) {
            acc[nb][0] *= inv0; acc[nb][1] *= inv0;
            acc[nb][2] *= inv1; acc[nb][3] *= inv1;
        }
        float* Osm = &sm[OFF_P];
        #pragma unroll
        for (int nb = 0; nb < 8; nb++) {
            int d = nb*8 + 2*t;
            Osm[(d  )*OSTR + r0    ] = acc[nb][0];
            Osm[(d+1)*OSTR + r0    ] = acc[nb][1];
            Osm[(d  )*OSTR + r0 + 8] = acc[nb][2];
            Osm[(d+1)*OSTR + r0 + 8] = acc[nb][3];
        }
        __syncthreads();
        const size_t obase = ((size_t)b*EMB + h*HD) * NTOK + qbase;
        for (int i = tid; i < 64*128; i += 256) {
            int d = i >> 7, n = i & 127;
            out[obase + (size_t)d * NTOK + n] = Osm[d*OSTR + n];
        }
    }
}

// ---------------------------------------------------------------------------
extern "C" void kernel_launch(void* const* d_in, const int* in_sizes, int n_in,
                              void* d_out, int out_size)
{
    const float* query = (const float*)d_in[0];
    const float* key   = (const float*)d_in[1];
    const float* Wq    = (const float*)d_in[2];
    const float* bq    = (const float*)d_in[3];
    const float* Wk    = (const float*)d_in[4];
    const float* bk    = (const float*)d_in[5];
    const float* Wv    = (const float*)d_in[6];
    const float* bv    = (const float*)d_in[7];
    float* out = (float*)d_out;

    dim3 pgrid(64, 4, 3);
    proj_mma<<<pgrid, 256>>>(query, key, Wq, bq, Wk, bk, Wv, bv);

    const int attn_smem = SMF * (int)sizeof(float);   // 110,592 B
    cudaFuncSetAttribute(attn_mma,
                         cudaFuncAttributeMaxDynamicSharedMemorySize, attn_smem);
    dim3 agrid(16, NH, 2);
    attn_mma<<<agrid, 256, attn_smem>>>(out);
}

// round 10
// speedup vs baseline: 2.1122x; 2.1122x over previous
#include <cuda_runtime.h>
#include <cuda_fp16.h>
#include <stdint.h>

#define NH   8
#define HD   64
#define NTOK 4096
#define EMB  512
#define CIN  512

// Scratch Q/K/V in [b][h][n][d] layout, fp16.  Q pre-scaled by 0.125*log2(e).
__device__ __half g_Q[2*NH*NTOK*HD];
__device__ __half g_K[2*NH*NTOK*HD];
__device__ __half g_V[2*NH*NTOK*HD];

// ---------------------------------------------------------------------------
__device__ __forceinline__ uint32_t f2tf(float x){
    uint32_t u; asm("cvt.rna.tf32.f32 %0, %1;" : "=r"(u) : "f"(x)); return u;
}
__device__ __forceinline__ float ex2f(float x){
    float r; asm("ex2.approx.ftz.f32 %0, %1;" : "=f"(r) : "f"(x)); return r;
}
__device__ __forceinline__ uint32_t smem_u32(const void* p) {
    uint32_t a;
    asm("{ .reg .u64 t; cvta.to.shared.u64 t, %1; cvt.u32.u64 %0, t; }" : "=r"(a) : "l"(p));
    return a;
}
// tf32 mma (projection)
__device__ __forceinline__ void mma8(float* c, const uint32_t* a, uint32_t b0, uint32_t b1){
    asm volatile("mma.sync.aligned.m16n8k8.row.col.f32.tf32.tf32.f32 "
        "{%0,%1,%2,%3},{%4,%5,%6,%7},{%8,%9},{%0,%1,%2,%3};"
        : "+f"(c[0]),"+f"(c[1]),"+f"(c[2]),"+f"(c[3])
        : "r"(a[0]),"r"(a[1]),"r"(a[2]),"r"(a[3]),"r"(b0),"r"(b1));
}
// fp16 mma, fp32 accum (attention)
__device__ __forceinline__ void mma16(float* c, const uint32_t* a, uint32_t b0, uint32_t b1){
    asm volatile("mma.sync.aligned.m16n8k16.row.col.f32.f16.f16.f32 "
        "{%0,%1,%2,%3},{%4,%5,%6,%7},{%8,%9},{%0,%1,%2,%3};"
        : "+f"(c[0]),"+f"(c[1]),"+f"(c[2]),"+f"(c[3])
        : "r"(a[0]),"r"(a[1]),"r"(a[2]),"r"(a[3]),"r"(b0),"r"(b1));
}
#define LDSM4(r, a) \
    asm volatile("ldmatrix.sync.aligned.m8n8.x4.shared.b16 {%0,%1,%2,%3}, [%4];" \
        : "=r"((r)[0]),"=r"((r)[1]),"=r"((r)[2]),"=r"((r)[3]) : "r"(a))
#define LDSM4T(r, a) \
    asm volatile("ldmatrix.sync.aligned.m8n8.x4.trans.shared.b16 {%0,%1,%2,%3}, [%4];" \
        : "=r"((r)[0]),"=r"((r)[1]),"=r"((r)[2]),"=r"((r)[3]) : "r"(a))

// ---------------------------------------------------------------------------
// Projection (tf32 mma): O[b][h][n][d] = X_tok @ W^T + bias, fp16 output.
// ---------------------------------------------------------------------------
__global__ __launch_bounds__(256, 2) void proj_mma(
    const float* __restrict__ query, const float* __restrict__ key,
    const float* __restrict__ Wq, const float* __restrict__ bq,
    const float* __restrict__ Wk, const float* __restrict__ bk,
    const float* __restrict__ Wv, const float* __restrict__ bv)
{
    const int z = blockIdx.z;
    const float* X    = (z == 0) ? query : key;
    const float* W    = (z == 0) ? Wq : (z == 1 ? Wk : Wv);
    const float* bias = (z == 0) ? bq : (z == 1 ? bk : bv);
    __half* O         = (z == 0) ? g_Q : (z == 1 ? g_K : g_V);
    const float osc   = (z == 0) ? 0.18033688011112042f : 1.0f;  // 0.125*log2(e)

    const int b  = blockIdx.x >> 5;
    const int n0 = (blockIdx.x & 31) * 128;
    const int e0 = blockIdx.y * 128;

    __shared__ uint32_t Au[16*132];
    __shared__ uint32_t Wu[16*132];

    const int tid = threadIdx.x, lane = tid & 31, w = tid >> 5;
    const int g = lane >> 2, t = lane & 3;
    const int wm = w >> 1, wn = w & 1;

    float acc[2][8][4];
    #pragma unroll
    for (int mb = 0; mb < 2; mb++)
        #pragma unroll
        for (int nb = 0; nb < 8; nb++)
            #pragma unroll
            for (int c = 0; c < 4; c++) acc[mb][nb][c] = 0.f;

    const size_t xbase = (size_t)b * CIN * NTOK;

    for (int c0 = 0; c0 < CIN; c0 += 16) {
        __syncthreads();
        #pragma unroll
        for (int it = 0; it < 2; it++) {
            int i = tid + it*256;
            int c = i >> 5, nq = (i & 31) * 4;
            float4 v = *(const float4*)&X[xbase + (size_t)(c0 + c) * NTOK + n0 + nq];
            uint4 u = { f2tf(v.x), f2tf(v.y), f2tf(v.z), f2tf(v.w) };
            *(uint4*)&Au[c*132 + nq] = u;
        }
        #pragma unroll
        for (int it = 0; it < 2; it++) {
            int i = tid + it*256;
            int e = i >> 2, cq = (i & 3) * 4;
            float4 v = *(const float4*)&W[(size_t)(e0 + e) * CIN + c0 + cq];
            Wu[(cq+0)*132 + e] = f2tf(v.x);
            Wu[(cq+1)*132 + e] = f2tf(v.y);
            Wu[(cq+2)*132 + e] = f2tf(v.z);
            Wu[(cq+3)*132 + e] = f2tf(v.w);
        }
        __syncthreads();

        #pragma unroll
        for (int kc = 0; kc < 2; kc++) {
            uint32_t a[2][4];
            #pragma unroll
            for (int mb = 0; mb < 2; mb++) {
                int r = wm*32 + mb*16;
                a[mb][0] = Au[(kc*8+t  )*132 + r + g];
                a[mb][1] = Au[(kc*8+t  )*132 + r + g + 8];
                a[mb][2] = Au[(kc*8+t+4)*132 + r + g];
                a[mb][3] = Au[(kc*8+t+4)*132 + r + g + 8];
            }
            #pragma unroll
            for (int nb = 0; nb < 8; nb++) {
                int e = wn*64 + nb*8;
                uint32_t b0 = Wu[(kc*8+t  )*132 + e + g];
                uint32_t b1 = Wu[(kc*8+t+4)*132 + e + g];
                mma8(acc[0][nb], a[0], b0, b1);
                mma8(acc[1][nb], a[1], b0, b1);
            }
        }
    }

    #pragma unroll
    for (int mb = 0; mb < 2; mb++) {
        #pragma unroll
        for (int nb = 0; nb < 8; nb++) {
            int e = e0 + wn*64 + nb*8 + 2*t;
            float2 bb = *(const float2*)&bias[e];
            int h = e >> 6, d = e & 63;
            int n = n0 + wm*32 + mb*16 + g;
            __half* o0 = &O[(((size_t)b*NH + h)*NTOK + n)*HD + d];
            *(__half2*)o0 = __floats2half2_rn((acc[mb][nb][0] + bb.x) * osc,
                                              (acc[mb][nb][1] + bb.y) * osc);
            *(__half2*)(o0 + 8*HD) = __floats2half2_rn((acc[mb][nb][2] + bb.x) * osc,
                                                       (acc[mb][nb][3] + bb.y) * osc);
        }
    }
}

// ---------------------------------------------------------------------------
// Flash attention, fp16 mma + ldmatrix. 512 blocks (qt descending), 8 warps,
// 128-query tile, 64-key tiles.  All fragments loaded via LDSM (x4).
// smem (half units, 72-half padded rows): K[64][72], V[64][72], P/Q[128][72].
// ---------------------------------------------------------------------------
#define KSTR 72
#define OFF_K 0
#define OFF_V (64*KSTR)            // 4608
#define OFF_P (2*64*KSTR)          // 9216
#define SMH   (OFF_P + 128*KSTR)   // 18432 halves = 36864 B
#define OSTR  132

__global__ __launch_bounds__(256, 2) void attn_mma(float* __restrict__ out)
{
    const int qt = 31 - (int)blockIdx.x;   // big tiles first
    const int h  = blockIdx.y;
    const int b  = blockIdx.z;

    __shared__ __align__(16) __half smh[SMH];
    const uint32_t sbase = smem_u32(smh);

    const int tid = threadIdx.x, lane = tid & 31, w = tid >> 5;
    const int g = lane >> 2, t = lane & 3;
    const int r0 = w*16 + g;
    const int m  = lane >> 3, lr = lane & 7;

    // per-lane ldmatrix base addresses (byte offsets; row stride 144 B)
    const uint32_t aP = sbase + (uint32_t)(OFF_P*2) + (uint32_t)(w*16 + (m&1)*8 + lr)*144u + (uint32_t)((m>>1)*8)*2u;
    const uint32_t aK = sbase + (uint32_t)(OFF_K*2) + (uint32_t)((m>>1)*8 + lr)*144u + (uint32_t)((m&1)*8)*2u;
    const uint32_t aV = sbase + (uint32_t)(OFF_V*2) + (uint32_t)((m&1)*8 + lr)*144u + (uint32_t)((m>>1)*8)*2u;

    const size_t base  = ((size_t)(b*NH + h)) * NTOK * HD;
    const int    qbase = qt * 128;
    const __half* Kg = g_K + base;
    const __half* Vg = g_V + base;

    // stage Q (fp16, pre-scaled) into P region
    #pragma unroll
    for (int it = 0; it < 4; it++) {
        int i = tid + it*256, r = i >> 3, d0 = (i & 7) * 8;
        *(uint4*)&smh[OFF_P + r*KSTR + d0] =
            *(const uint4*)&g_Q[base + (size_t)(qbase + r)*HD + d0];
    }
    __syncthreads();

    // lift Q fragments: 4 k-chunks x 4 regs
    uint32_t qf[4][4];
    #pragma unroll
    for (int kc = 0; kc < 4; kc++) LDSM4(qf[kc], aP + (uint32_t)(kc*16)*2u);

    float acc[8][4];
    #pragma unroll
    for (int nb = 0; nb < 8; nb++)
        #pragma unroll
        for (int c = 0; c < 4; c++) acc[nb][c] = 0.f;
    float m0 = -1e30f, m1 = -1e30f, l0 = 0.f, l1 = 0.f;

    const int ntiles = 2*qt + 2;
    for (int j = 0; j < ntiles; j++) {
        const int n0 = j * 64;
        __syncthreads();
        // stage K,V tile (64 x 64 fp16 each): 16-byte copies
        #pragma unroll
        for (int it = 0; it < 2; it++) {
            int i = tid + it*256, r = i >> 3, d0 = (i & 7) * 8;
            *(uint4*)&smh[OFF_K + r*KSTR + d0] = *(const uint4*)&Kg[(size_t)(n0 + r)*HD + d0];
            *(uint4*)&smh[OFF_V + r*KSTR + d0] = *(const uint4*)&Vg[(size_t)(n0 + r)*HD + d0];
        }
        __syncthreads();

        // S = Q K^T : 16 rows x 64 keys per warp, K=64 in 4 chunks
        float s[8][4];
        #pragma unroll
        for (int nb = 0; nb < 8; nb++)
            #pragma unroll
            for (int c = 0; c < 4; c++) s[nb][c] = 0.f;
        #pragma unroll
        for (int kc = 0; kc < 4; kc++) {
            #pragma unroll
            for (int nbp = 0; nbp < 4; nbp++) {
                uint32_t kb[4];
                LDSM4(kb, aK + (uint32_t)(nbp*16)*144u + (uint32_t)(kc*16)*2u);
                mma16(s[2*nbp  ], qf[kc], kb[0], kb[1]);
                mma16(s[2*nbp+1], qf[kc], kb[2], kb[3]);
            }
        }

        if (j >= 2*qt) {   // diagonal tiles: causal mask
            const int row = qbase + r0;
            #pragma unroll
            for (int nb = 0; nb < 8; nb++) {
                int col = n0 + nb*8 + 2*t;
                if (col     > row  ) s[nb][0] = -1e30f;
                if (col + 1 > row  ) s[nb][1] = -1e30f;
                if (col     > row+8) s[nb][2] = -1e30f;
                if (col + 1 > row+8) s[nb][3] = -1e30f;
            }
        }

        // online softmax (rows r0, r0+8), base-2 domain
        float mx0 = -1e30f, mx1 = -1e30f;
        #pragma unroll
        for (int nb = 0; nb < 8; nb++) {
            mx0 = fmaxf(mx0, fmaxf(s[nb][0], s[nb][1]));
            mx1 = fmaxf(mx1, fmaxf(s[nb][2], s[nb][3]));
        }
        mx0 = fmaxf(mx0, __shfl_xor_sync(0xffffffffu, mx0, 1));
        mx0 = fmaxf(mx0, __shfl_xor_sync(0xffffffffu, mx0, 2));
        mx1 = fmaxf(mx1, __shfl_xor_sync(0xffffffffu, mx1, 1));
        mx1 = fmaxf(mx1, __shfl_xor_sync(0xffffffffu, mx1, 2));
        float mn0 = fmaxf(m0, mx0), mn1 = fmaxf(m1, mx1);
        float sc0 = ex2f(m0 - mn0), sc1 = ex2f(m1 - mn1);
        float ps0 = 0.f, ps1 = 0.f;
        __half2* pr0 = (__half2*)&smh[OFF_P + ( r0  )*KSTR + 2*t];
        __half2* pr1 = (__half2*)&smh[OFF_P + (r0+8)*KSTR + 2*t];
        #pragma unroll
        for (int nb = 0; nb < 8; nb++) {
            float p0 = ex2f(s[nb][0]-mn0), p1 = ex2f(s[nb][1]-mn0);
            float p2 = ex2f(s[nb][2]-mn1), p3 = ex2f(s[nb][3]-mn1);
            ps0 += p0 + p1;  ps1 += p2 + p3;
            acc[nb][0] *= sc0; acc[nb][1] *= sc0;
            acc[nb][2] *= sc1; acc[nb][3] *= sc1;
            pr0[nb*4] = __floats2half2_rn(p0, p1);
            pr1[nb*4] = __floats2half2_rn(p2, p3);
        }
        ps0 += __shfl_xor_sync(0xffffffffu, ps0, 1);
        ps0 += __shfl_xor_sync(0xffffffffu, ps0, 2);
        ps1 += __shfl_xor_sync(0xffffffffu, ps1, 1);
        ps1 += __shfl_xor_sync(0xffffffffu, ps1, 2);
        l0 = l0*sc0 + ps0;  l1 = l1*sc1 + ps1;
        m0 = mn0;  m1 = mn1;
        __syncwarp();

        // O += P V : A = P rows (warp-private) via LDSM, B = V via LDSM.trans
        #pragma unroll
        for (int kc = 0; kc < 4; kc++) {
            uint32_t pa[4];
            LDSM4(pa, aP + (uint32_t)(kc*16)*2u);
            #pragma unroll
            for (int nbp = 0; nbp < 4; nbp++) {
                uint32_t vb[4];
                LDSM4T(vb, aV + (uint32_t)(kc*16)*144u + (uint32_t)(nbp*16)*2u);
                mma16(acc[2*nbp  ], pa, vb[0], vb[1]);
                mma16(acc[2*nbp+1], pa, vb[2], vb[3]);
            }
        }
    }

    // finalize: /l, stage transposed (fp32 overlay at smem base), write out[b][e][n]
    float inv0 = 1.f / l0, inv1 = 1.f / l1;
    #pragma unroll
    for (int nb = 0; nb < 8; nb++) {
        acc[nb][0] *= inv0; acc[nb][1] *= inv0;
        acc[nb][2] *= inv1; acc[nb][3] *= inv1;
    }
    __syncthreads();
    float* Osm = (float*)smh;
    #pragma unroll
    for (int nb = 0; nb < 8; nb++) {
        int d = nb*8 + 2*t;
        Osm[(d  )*OSTR + r0    ] = acc[nb][0];
        Osm[(d+1)*OSTR + r0    ] = acc[nb][1];
        Osm[(d  )*OSTR + r0 + 8] = acc[nb][2];
        Osm[(d+1)*OSTR + r0 + 8] = acc[nb][3];
    }
    __syncthreads();
    const size_t obase = ((size_t)b*EMB + h*HD) * NTOK + qbase;
    for (int i = tid; i < 64*128; i += 256) {
        int d = i >> 7, n = i & 127;
        out[obase + (size_t)d * NTOK + n] = Osm[d*OSTR + n];
    }
}

// ---------------------------------------------------------------------------
extern "C" void kernel_launch(void* const* d_in, const int* in_sizes, int n_in,
                              void* d_out, int out_size)
{
    const float* query = (const float*)d_in[0];
    const float* key   = (const float*)d_in[1];
    const float* Wq    = (const float*)d_in[2];
    const float* bq    = (const float*)d_in[3];
    const float* Wk    = (const float*)d_in[4];
    const float* bk    = (const float*)d_in[5];
    const float* Wv    = (const float*)d_in[6];
    const float* bv    = (const float*)d_in[7];
    float* out = (float*)d_out;

    dim3 pgrid(64, 4, 3);
    proj_mma<<<pgrid, 256>>>(query, key, Wq, bq, Wk, bk, Wv, bv);

    dim3 agrid(32, NH, 2);
    attn_mma<<<agrid, 256>>>(out);
}

// round 11
// speedup vs baseline: 2.6381x; 1.2490x over previous
#include <cuda_runtime.h>
#include <cuda_fp16.h>
#include <stdint.h>

#define NH   8
#define HD   64
#define NTOK 4096
#define EMB  512
#define CIN  512

// Scratch Q/K/V in [b][h][n][d] layout, fp16.  Q pre-scaled by 0.125*log2(e).
__device__ __half g_Q[2*NH*NTOK*HD];
__device__ __half g_K[2*NH*NTOK*HD];
__device__ __half g_V[2*NH*NTOK*HD];

// ---------------------------------------------------------------------------
__device__ __forceinline__ float ex2f(float x){
    float r; asm("ex2.approx.ftz.f32 %0, %1;" : "=f"(r) : "f"(x)); return r;
}
__device__ __forceinline__ uint32_t smem_u32(const void* p) {
    uint32_t a;
    asm("{ .reg .u64 t; cvta.to.shared.u64 t, %1; cvt.u32.u64 %0, t; }" : "=r"(a) : "l"(p));
    return a;
}
__device__ __forceinline__ uint32_t pack2(float x, float y){
    __half2 h = __floats2half2_rn(x, y);
    return *(uint32_t*)&h;
}
// fp16 mma, fp32 accum
__device__ __forceinline__ void mma16(float* c, const uint32_t* a, uint32_t b0, uint32_t b1){
    asm volatile("mma.sync.aligned.m16n8k16.row.col.f32.f16.f16.f32 "
        "{%0,%1,%2,%3},{%4,%5,%6,%7},{%8,%9},{%0,%1,%2,%3};"
        : "+f"(c[0]),"+f"(c[1]),"+f"(c[2]),"+f"(c[3])
        : "r"(a[0]),"r"(a[1]),"r"(a[2]),"r"(a[3]),"r"(b0),"r"(b1));
}
#define LDSM4(r, a) \
    asm volatile("ldmatrix.sync.aligned.m8n8.x4.shared.b16 {%0,%1,%2,%3}, [%4];" \
        : "=r"((r)[0]),"=r"((r)[1]),"=r"((r)[2]),"=r"((r)[3]) : "r"(a))
#define LDSM4T(r, a) \
    asm volatile("ldmatrix.sync.aligned.m8n8.x4.trans.shared.b16 {%0,%1,%2,%3}, [%4];" \
        : "=r"((r)[0]),"=r"((r)[1]),"=r"((r)[2]),"=r"((r)[3]) : "r"(a))
#define CP16(dst, src) asm volatile("cp.async.cg.shared.global [%0], [%1], 16;" :: "r"(dst), "l"(src) : "memory")
#define CP_COMMIT()    asm volatile("cp.async.commit_group;" ::: "memory")
#define CP_WAIT0()     asm volatile("cp.async.wait_group 0;" ::: "memory")

// ---------------------------------------------------------------------------
// Projection (fp16 mma + ldmatrix): O[b][h][n][d] = X_tok @ W^T + bias.
// X gmem [c][n] -> smem [c][n] (natural) -> A frags via ldmatrix.trans.
// W gmem [e][c] -> smem [e][c] (natural) -> B frags via ldmatrix.
// 128n x 128e tile, BK=16, register-prefetch double-buffered k-tiles.
// ---------------------------------------------------------------------------
#define XSTR 136
#define WSTR 24

__global__ __launch_bounds__(256, 2) void proj_mma(
    const float* __restrict__ query, const float* __restrict__ key,
    const float* __restrict__ Wq, const float* __restrict__ bq,
    const float* __restrict__ Wk, const float* __restrict__ bk,
    const float* __restrict__ Wv, const float* __restrict__ bv)
{
    const int z = blockIdx.z;
    const float* X    = (z == 0) ? query : key;
    const float* W    = (z == 0) ? Wq : (z == 1 ? Wk : Wv);
    const float* bias = (z == 0) ? bq : (z == 1 ? bk : bv);
    __half* O         = (z == 0) ? g_Q : (z == 1 ? g_K : g_V);
    const float osc   = (z == 0) ? 0.18033688011112042f : 1.0f;  // 0.125*log2(e)

    const int b  = blockIdx.x >> 5;
    const int n0 = (blockIdx.x & 31) * 128;
    const int e0 = blockIdx.y * 128;

    __shared__ __align__(16) __half Xs[2][16*XSTR];
    __shared__ __align__(16) __half Ws[2][128*WSTR];

    const int tid = threadIdx.x, lane = tid & 31, w = tid >> 5;
    const int g = lane >> 2, t = lane & 3;
    const int wm = w >> 1, wn = w & 1;
    const int i8 = lane >> 3, lr = lane & 7;

    // staging map: X row c=tid>>4, cols (tid&15)*8 ; W row e=tid>>1, cols (tid&1)*8
    const int xc = tid >> 4, xn = (tid & 15) * 8;
    const int we = tid >> 1, wc = (tid & 1) * 8;

    // ldmatrix lane offsets (in halves)
    // A (trans, smem [k][m]): group i: k-row (i>>1)*8+lr, m-col (i&1)*8
    const uint32_t aoff = (uint32_t)(((i8 >> 1)*8 + lr)*XSTR + (i8 & 1)*8);
    // B (plain, smem [e][c]): group i: e-row (i>>1)*8+lr, k-col (i&1)*8
    const uint32_t boff = (uint32_t)(((i8 >> 1)*8 + lr)*WSTR + (i8 & 1)*8);

    const size_t xbase = (size_t)b * CIN * NTOK;

    float acc[2][8][4];
    #pragma unroll
    for (int mb = 0; mb < 2; mb++)
        #pragma unroll
        for (int nb = 0; nb < 8; nb++)
            #pragma unroll
            for (int c = 0; c < 4; c++) acc[mb][nb][c] = 0.f;

    // prefetch k-tile 0
    float4 xv0 = *(const float4*)&X[xbase + (size_t)xc * NTOK + n0 + xn];
    float4 xv1 = *(const float4*)&X[xbase + (size_t)xc * NTOK + n0 + xn + 4];
    float4 wv0 = *(const float4*)&W[(size_t)(e0 + we) * CIN + wc];
    float4 wv1 = *(const float4*)&W[(size_t)(e0 + we) * CIN + wc + 4];

    for (int kt = 0; kt < CIN/16; kt++) {
        const int cur = kt & 1;
        // store prefetched tile
        {
            uint4 ux = { pack2(xv0.x, xv0.y), pack2(xv0.z, xv0.w),
                         pack2(xv1.x, xv1.y), pack2(xv1.z, xv1.w) };
            *(uint4*)&Xs[cur][xc*XSTR + xn] = ux;
            uint4 uw = { pack2(wv0.x, wv0.y), pack2(wv0.z, wv0.w),
                         pack2(wv1.x, wv1.y), pack2(wv1.z, wv1.w) };
            *(uint4*)&Ws[cur][we*WSTR + wc] = uw;
        }
        __syncthreads();
        if (kt + 1 < CIN/16) {
            const int c0 = (kt + 1) * 16;
            xv0 = *(const float4*)&X[xbase + (size_t)(c0 + xc) * NTOK + n0 + xn];
            xv1 = *(const float4*)&X[xbase + (size_t)(c0 + xc) * NTOK + n0 + xn + 4];
            wv0 = *(const float4*)&W[(size_t)(e0 + we) * CIN + c0 + wc];
            wv1 = *(const float4*)&W[(size_t)(e0 + we) * CIN + c0 + wc + 4];
        }
        // compute on buffer cur
        const uint32_t sX = smem_u32(&Xs[cur][0]);
        const uint32_t sW = smem_u32(&Ws[cur][0]);
        uint32_t a[2][4];
        #pragma unroll
        for (int mb = 0; mb < 2; mb++)
            LDSM4T(a[mb], sX + 2u*(aoff + (uint32_t)(wm*32 + mb*16)));
        #pragma unroll
        for (int nbp = 0; nbp < 4; nbp++) {
            uint32_t bf[4];
            LDSM4(bf, sW + 2u*(boff + (uint32_t)((wn*64 + nbp*16)*WSTR)));
            #pragma unroll
            for (int mb = 0; mb < 2; mb++) {
                mma16(acc[mb][2*nbp  ], a[mb], bf[0], bf[1]);
                mma16(acc[mb][2*nbp+1], a[mb], bf[2], bf[3]);
            }
        }
    }

    // epilogue: +bias, *osc, fp16 store in [b][h][n][d]
    #pragma unroll
    for (int mb = 0; mb < 2; mb++) {
        #pragma unroll
        for (int nb = 0; nb < 8; nb++) {
            int e = e0 + wn*64 + nb*8 + 2*t;
            float2 bb = *(const float2*)&bias[e];
            int h = e >> 6, d = e & 63;
            int n = n0 + wm*32 + mb*16 + g;
            __half* o0 = &O[(((size_t)b*NH + h)*NTOK + n)*HD + d];
            *(__half2*)o0 = __floats2half2_rn((acc[mb][nb][0] + bb.x) * osc,
                                              (acc[mb][nb][1] + bb.y) * osc);
            *(__half2*)(o0 + 8*HD) = __floats2half2_rn((acc[mb][nb][2] + bb.x) * osc,
                                                       (acc[mb][nb][3] + bb.y) * osc);
        }
    }
}

// ---------------------------------------------------------------------------
// Flash attention, fp16 mma + ldmatrix, cp.async double-buffered K/V.
// 512 blocks (qt descending), 8 warps, 128-query tile, 64-key tiles.
// smem (halves, 72-padded rows): K0,K1,V0,V1 [64][72], P/Q [128][72].
// ---------------------------------------------------------------------------
#define KSTR 72
#define OFF_K0 0
#define OFF_K1 (64*KSTR)           // 4608
#define OFF_V0 (2*64*KSTR)         // 9216
#define OFF_V1 (3*64*KSTR)         // 13824
#define OFF_P  (4*64*KSTR)         // 18432
#define SMH    (OFF_P + 128*KSTR)  // 27648 halves = 55296 B
#define OSTR   132

__device__ __forceinline__ void stage_kv_async(uint32_t sb, const __half* Kg, const __half* Vg,
                                               int n0, int kOff, int vOff, int tid)
{
    #pragma unroll
    for (int it = 0; it < 2; it++) {
        int i = tid + it*256, r = i >> 3, c8 = (i & 7) * 8;
        CP16(sb + (uint32_t)(kOff + r*KSTR + c8)*2u, Kg + (size_t)(n0 + r)*HD + c8);
        CP16(sb + (uint32_t)(vOff + r*KSTR + c8)*2u, Vg + (size_t)(n0 + r)*HD + c8);
    }
}

__global__ __launch_bounds__(256, 2) void attn_mma(float* __restrict__ out)
{
    const int qt = 31 - (int)blockIdx.x;   // big tiles first
    const int h  = blockIdx.y;
    const int b  = blockIdx.z;

    extern __shared__ __align__(16) __half smh[];
    const uint32_t sbase = smem_u32(smh);

    const int tid = threadIdx.x, lane = tid & 31, w = tid >> 5;
    const int g = lane >> 2, t = lane & 3;
    const int r0 = w*16 + g;
    const int m  = lane >> 3, lr = lane & 7;

    // per-lane ldmatrix base addresses (byte offsets; row stride 144 B)
    const uint32_t aP = sbase + (uint32_t)(OFF_P*2) + (uint32_t)(w*16 + (m&1)*8 + lr)*144u + (uint32_t)((m>>1)*8)*2u;
    const uint32_t aKo = (uint32_t)((m>>1)*8 + lr)*144u + (uint32_t)((m&1)*8)*2u;   // + buf base
    const uint32_t aVo = (uint32_t)((m&1)*8 + lr)*144u + (uint32_t)((m>>1)*8)*2u;   // + buf base

    const size_t base  = ((size_t)(b*NH + h)) * NTOK * HD;
    const int    qbase = qt * 128;
    const __half* Kg = g_K + base;
    const __half* Vg = g_V + base;

    // stage K/V tile 0 (async) and Q (sync)
    stage_kv_async(sbase, Kg, Vg, 0, OFF_K0, OFF_V0, tid);
    CP_COMMIT();
    #pragma unroll
    for (int it = 0; it < 4; it++) {
        int i = tid + it*256, r = i >> 3, d0 = (i & 7) * 8;
        *(uint4*)&smh[OFF_P + r*KSTR + d0] =
            *(const uint4*)&g_Q[base + (size_t)(qbase + r)*HD + d0];
    }
    __syncthreads();

    // lift Q fragments: 4 k-chunks x 4 regs
    uint32_t qf[4][4];
    #pragma unroll
    for (int kc = 0; kc < 4; kc++) LDSM4(qf[kc], aP + (uint32_t)(kc*16)*2u);

    float acc[8][4];
    #pragma unroll
    for (int nb = 0; nb < 8; nb++)
        #pragma unroll
        for (int c = 0; c < 4; c++) acc[nb][c] = 0.f;
    float m0 = -1e30f, m1 = -1e30f, l0 = 0.f, l1 = 0.f;

    const int ntiles = 2*qt + 2;
    for (int j = 0; j < ntiles; j++) {
        const int n0 = j * 64;
        const uint32_t kb = sbase + (uint32_t)(((j & 1) ? OFF_K1 : OFF_K0) * 2);
        const uint32_t vb = sbase + (uint32_t)(((j & 1) ? OFF_V1 : OFF_V0) * 2);

        CP_WAIT0();
        __syncthreads();
        if (j + 1 < ntiles) {
            stage_kv_async(sbase, Kg, Vg, (j+1)*64,
                           ((j+1) & 1) ? OFF_K1 : OFF_K0,
                           ((j+1) & 1) ? OFF_V1 : OFF_V0, tid);
            CP_COMMIT();
        }

        // S = Q K^T : 16 rows x 64 keys per warp, K=64 in 4 chunks
        float s[8][4];
        #pragma unroll
        for (int nb = 0; nb < 8; nb++)
            #pragma unroll
            for (int c = 0; c < 4; c++) s[nb][c] = 0.f;
        #pragma unroll
        for (int kc = 0; kc < 4; kc++) {
            #pragma unroll
            for (int nbp = 0; nbp < 4; nbp++) {
                uint32_t kf[4];
                LDSM4(kf, kb + aKo + (uint32_t)(nbp*16)*144u + (uint32_t)(kc*16)*2u);
                mma16(s[2*nbp  ], qf[kc], kf[0], kf[1]);
                mma16(s[2*nbp+1], qf[kc], kf[2], kf[3]);
            }
        }

        if (j >= 2*qt) {   // diagonal tiles: causal mask
            const int row = qbase + r0;
            #pragma unroll
            for (int nb = 0; nb < 8; nb++) {
                int col = n0 + nb*8 + 2*t;
                if (col     > row  ) s[nb][0] = -1e30f;
                if (col + 1 > row  ) s[nb][1] = -1e30f;
                if (col     > row+8) s[nb][2] = -1e30f;
                if (col + 1 > row+8) s[nb][3] = -1e30f;
            }
        }

        // online softmax (rows r0, r0+8), base-2 domain
        float mx0 = -1e30f, mx1 = -1e30f;
        #pragma unroll
        for (int nb = 0; nb < 8; nb++) {
            mx0 = fmaxf(mx0, fmaxf(s[nb][0], s[nb][1]));
            mx1 = fmaxf(mx1, fmaxf(s[nb][2], s[nb][3]));
        }
        mx0 = fmaxf(mx0, __shfl_xor_sync(0xffffffffu, mx0, 1));
        mx0 = fmaxf(mx0, __shfl_xor_sync(0xffffffffu, mx0, 2));
        mx1 = fmaxf(mx1, __shfl_xor_sync(0xffffffffu, mx1, 1));
        mx1 = fmaxf(mx1, __shfl_xor_sync(0xffffffffu, mx1, 2));
        float mn0 = fmaxf(m0, mx0), mn1 = fmaxf(m1, mx1);
        float sc0 = ex2f(m0 - mn0), sc1 = ex2f(m1 - mn1);
        float ps0 = 0.f, ps1 = 0.f;
        __half2* pr0 = (__half2*)&smh[OFF_P + ( r0  )*KSTR + 2*t];
        __half2* pr1 = (__half2*)&smh[OFF_P + (r0+8)*KSTR + 2*t];
        #pragma unroll
        for (int nb = 0; nb < 8; nb++) {
            float p0 = ex2f(s[nb][0]-mn0), p1 = ex2f(s[nb][1]-mn0);
            float p2 = ex2f(s[nb][2]-mn1), p3 = ex2f(s[nb][3]-mn1);
            ps0 += p0 + p1;  ps1 += p2 + p3;
            acc[nb][0] *= sc0; acc[nb][1] *= sc0;
            acc[nb][2] *= sc1; acc[nb][3] *= sc1;
            pr0[nb*4] = __floats2half2_rn(p0, p1);
            pr1[nb*4] = __floats2half2_rn(p2, p3);
        }
        ps0 += __shfl_xor_sync(0xffffffffu, ps0, 1);
        ps0 += __shfl_xor_sync(0xffffffffu, ps0, 2);
        ps1 += __shfl_xor_sync(0xffffffffu, ps1, 1);
        ps1 += __shfl_xor_sync(0xffffffffu, ps1, 2);
        l0 = l0*sc0 + ps0;  l1 = l1*sc1 + ps1;
        m0 = mn0;  m1 = mn1;
        __syncwarp();

        // O += P V : A = P rows (warp-private) via LDSM, B = V via LDSM.trans
        #pragma unroll
        for (int kc = 0; kc < 4; kc++) {
            uint32_t pa[4];
            LDSM4(pa, aP + (uint32_t)(kc*16)*2u);
            #pragma unroll
            for (int nbp = 0; nbp < 4; nbp++) {
                uint32_t vf[4];
                LDSM4T(vf, vb + aVo + (uint32_t)(kc*16)*144u + (uint32_t)(nbp*16)*2u);
                mma16(acc[2*nbp  ], pa, vf[0], vf[1]);
                mma16(acc[2*nbp+1], pa, vf[2], vf[3]);
            }
        }
    }

    // finalize: /l, stage transposed (fp32 overlay), coalesced write out[b][e][n]
    float inv0 = 1.f / l0, inv1 = 1.f / l1;
    #pragma unroll
    for (int nb = 0; nb < 8; nb++) {
        acc[nb][0] *= inv0; acc[nb][1] *= inv0;
        acc[nb][2] *= inv1; acc[nb][3] *= inv1;
    }
    __syncthreads();
    float* Osm = (float*)smh;
    #pragma unroll
    for (int nb = 0; nb < 8; nb++) {
        int d = nb*8 + 2*t;
        Osm[(d  )*OSTR + r0    ] = acc[nb][0];
        Osm[(d+1)*OSTR + r0    ] = acc[nb][1];
        Osm[(d  )*OSTR + r0 + 8] = acc[nb][2];
        Osm[(d+1)*OSTR + r0 + 8] = acc[nb][3];
    }
    __syncthreads();
    const size_t obase = ((size_t)b*EMB + h*HD) * NTOK + qbase;
    for (int i = tid; i < 64*128; i += 256) {
        int d = i >> 7, n = i & 127;
        out[obase + (size_t)d * NTOK + n] = Osm[d*OSTR + n];
    }
}

// ---------------------------------------------------------------------------
extern "C" void kernel_launch(void* const* d_in, const int* in_sizes, int n_in,
                              void* d_out, int out_size)
{
    const float* query = (const float*)d_in[0];
    const float* key   = (const float*)d_in[1];
    const float* Wq    = (const float*)d_in[2];
    const float* bq    = (const float*)d_in[3];
    const float* Wk    = (const float*)d_in[4];
    const float* bk    = (const float*)d_in[5];
    const float* Wv    = (const float*)d_in[6];
    const float* bv    = (const float*)d_in[7];
    float* out = (float*)d_out;

    dim3 pgrid(64, 4, 3);
    proj_mma<<<pgrid, 256>>>(query, key, Wq, bq, Wk, bk, Wv, bv);

    const int attn_smem = SMH * (int)sizeof(__half);   // 55,296 B
    cudaFuncSetAttribute(attn_mma,
                         cudaFuncAttributeMaxDynamicSharedMemorySize, attn_smem);
    dim3 agrid(32, NH, 2);
    attn_mma<<<agrid, 256, attn_smem>>>(out);
}

// round 13
// speedup vs baseline: 2.9294x; 1.1104x over previous
#include <cuda_runtime.h>
#include <cuda_fp16.h>
#include <stdint.h>

#define NH   8
#define HD   64
#define NTOK 4096
#define EMB  512
#define CIN  512

// Scratch Q/K/V in [b][h][n][d] layout, fp16.  Q pre-scaled by 0.125*log2(e).
__device__ __half g_Q[2*NH*NTOK*HD];
__device__ __half g_K[2*NH*NTOK*HD];
__device__ __half g_V[2*NH*NTOK*HD];

// ---------------------------------------------------------------------------
__device__ __forceinline__ float ex2f(float x){
    float r; asm("ex2.approx.ftz.f32 %0, %1;" : "=f"(r) : "f"(x)); return r;
}
__device__ __forceinline__ uint32_t smem_u32(const void* p) {
    uint32_t a;
    asm("{ .reg .u64 t; cvta.to.shared.u64 t, %1; cvt.u32.u64 %0, t; }" : "=r"(a) : "l"(p));
    return a;
}
__device__ __forceinline__ uint32_t pack2(float x, float y){
    __half2 h = __floats2half2_rn(x, y);
    return *(uint32_t*)&h;
}
// fp16 mma, fp32 accum
__device__ __forceinline__ void mma16(float* c, const uint32_t* a, uint32_t b0, uint32_t b1){
    asm volatile("mma.sync.aligned.m16n8k16.row.col.f32.f16.f16.f32 "
        "{%0,%1,%2,%3},{%4,%5,%6,%7},{%8,%9},{%0,%1,%2,%3};"
        : "+f"(c[0]),"+f"(c[1]),"+f"(c[2]),"+f"(c[3])
        : "r"(a[0]),"r"(a[1]),"r"(a[2]),"r"(a[3]),"r"(b0),"r"(b1));
}
#define LDSM4(r, a) \
    asm volatile("ldmatrix.sync.aligned.m8n8.x4.shared.b16 {%0,%1,%2,%3}, [%4];" \
        : "=r"((r)[0]),"=r"((r)[1]),"=r"((r)[2]),"=r"((r)[3]) : "r"(a))
#define LDSM4T(r, a) \
    asm volatile("ldmatrix.sync.aligned.m8n8.x4.trans.shared.b16 {%0,%1,%2,%3}, [%4];" \
        : "=r"((r)[0]),"=r"((r)[1]),"=r"((r)[2]),"=r"((r)[3]) : "r"(a))
#define CP16(dst, src) asm volatile("cp.async.cg.shared.global [%0], [%1], 16;" :: "r"(dst), "l"(src) : "memory")
#define CP_COMMIT()    asm volatile("cp.async.commit_group;" ::: "memory")
#define CP_WAIT0()     asm volatile("cp.async.wait_group 0;" ::: "memory")

// ---------------------------------------------------------------------------
// Projection (fp16 mma + ldmatrix): O[b][h][n][d] = X_tok @ W^T + bias.
// (unchanged from round 11: ~60 us, near memory floor)
// ---------------------------------------------------------------------------
#define XSTR 136
#define WSTR 24

__global__ __launch_bounds__(256, 2) void proj_mma(
    const float* __restrict__ query, const float* __restrict__ key,
    const float* __restrict__ Wq, const float* __restrict__ bq,
    const float* __restrict__ Wk, const float* __restrict__ bk,
    const float* __restrict__ Wv, const float* __restrict__ bv)
{
    const int z = blockIdx.z;
    const float* X    = (z == 0) ? query : key;
    const float* W    = (z == 0) ? Wq : (z == 1 ? Wk : Wv);
    const float* bias = (z == 0) ? bq : (z == 1 ? bk : bv);
    __half* O         = (z == 0) ? g_Q : (z == 1 ? g_K : g_V);
    const float osc   = (z == 0) ? 0.18033688011112042f : 1.0f;  // 0.125*log2(e)

    const int b  = blockIdx.x >> 5;
    const int n0 = (blockIdx.x & 31) * 128;
    const int e0 = blockIdx.y * 128;

    __shared__ __align__(16) __half Xs[2][16*XSTR];
    __shared__ __align__(16) __half Ws[2][128*WSTR];

    const int tid = threadIdx.x, lane = tid & 31, w = tid >> 5;
    const int g = lane >> 2, t = lane & 3;
    const int wm = w >> 1, wn = w & 1;
    const int i8 = lane >> 3, lr = lane & 7;

    const int xc = tid >> 4, xn = (tid & 15) * 8;
    const int we = tid >> 1, wc = (tid & 1) * 8;

    const uint32_t aoff = (uint32_t)(((i8 >> 1)*8 + lr)*XSTR + (i8 & 1)*8);
    const uint32_t boff = (uint32_t)(((i8 >> 1)*8 + lr)*WSTR + (i8 & 1)*8);

    const size_t xbase = (size_t)b * CIN * NTOK;

    float acc[2][8][4];
    #pragma unroll
    for (int mb = 0; mb < 2; mb++)
        #pragma unroll
        for (int nb = 0; nb < 8; nb++)
            #pragma unroll
            for (int c = 0; c < 4; c++) acc[mb][nb][c] = 0.f;

    float4 xv0 = *(const float4*)&X[xbase + (size_t)xc * NTOK + n0 + xn];
    float4 xv1 = *(const float4*)&X[xbase + (size_t)xc * NTOK + n0 + xn + 4];
    float4 wv0 = *(const float4*)&W[(size_t)(e0 + we) * CIN + wc];
    float4 wv1 = *(const float4*)&W[(size_t)(e0 + we) * CIN + wc + 4];

    for (int kt = 0; kt < CIN/16; kt++) {
        const int cur = kt & 1;
        {
            uint4 ux = { pack2(xv0.x, xv0.y), pack2(xv0.z, xv0.w),
                         pack2(xv1.x, xv1.y), pack2(xv1.z, xv1.w) };
            *(uint4*)&Xs[cur][xc*XSTR + xn] = ux;
            uint4 uw = { pack2(wv0.x, wv0.y), pack2(wv0.z, wv0.w),
                         pack2(wv1.x, wv1.y), pack2(wv1.z, wv1.w) };
            *(uint4*)&Ws[cur][we*WSTR + wc] = uw;
        }
        __syncthreads();
        if (kt + 1 < CIN/16) {
            const int c0 = (kt + 1) * 16;
            xv0 = *(const float4*)&X[xbase + (size_t)(c0 + xc) * NTOK + n0 + xn];
            xv1 = *(const float4*)&X[xbase + (size_t)(c0 + xc) * NTOK + n0 + xn + 4];
            wv0 = *(const float4*)&W[(size_t)(e0 + we) * CIN + c0 + wc];
            wv1 = *(const float4*)&W[(size_t)(e0 + we) * CIN + c0 + wc + 4];
        }
        const uint32_t sX = smem_u32(&Xs[cur][0]);
        const uint32_t sW = smem_u32(&Ws[cur][0]);
        uint32_t a[2][4];
        #pragma unroll
        for (int mb = 0; mb < 2; mb++)
            LDSM4T(a[mb], sX + 2u*(aoff + (uint32_t)(wm*32 + mb*16)));
        #pragma unroll
        for (int nbp = 0; nbp < 4; nbp++) {
            uint32_t bf[4];
            LDSM4(bf, sW + 2u*(boff + (uint32_t)((wn*64 + nbp*16)*WSTR)));
            #pragma unroll
            for (int mb = 0; mb < 2; mb++) {
                mma16(acc[mb][2*nbp  ], a[mb], bf[0], bf[1]);
                mma16(acc[mb][2*nbp+1], a[mb], bf[2], bf[3]);
            }
        }
    }

    #pragma unroll
    for (int mb = 0; mb < 2; mb++) {
        #pragma unroll
        for (int nb = 0; nb < 8; nb++) {
            int e = e0 + wn*64 + nb*8 + 2*t;
            float2 bb = *(const float2*)&bias[e];
            int h = e >> 6, d = e & 63;
            int n = n0 + wm*32 + mb*16 + g;
            __half* o0 = &O[(((size_t)b*NH + h)*NTOK + n)*HD + d];
            *(__half2*)o0 = __floats2half2_rn((acc[mb][nb][0] + bb.x) * osc,
                                              (acc[mb][nb][1] + bb.y) * osc);
            *(__half2*)(o0 + 8*HD) = __floats2half2_rn((acc[mb][nb][2] + bb.x) * osc,
                                                       (acc[mb][nb][3] + bb.y) * osc);
        }
    }
}

// ---------------------------------------------------------------------------
// Flash attention, fp16 mma + ldmatrix, cp.async double-buffered K/V.
// P stays in REGISTERS (S C-frag layout == PV A-frag layout) — no smem P.
// Lazy softmax: warp-vote skips max shuffles + acc rescale when running max
// already dominates; l reduced across lanes only in the epilogue.
// ---------------------------------------------------------------------------
#define KSTR 72
#define OFF_K0 0
#define OFF_K1 (64*KSTR)           // 4608
#define OFF_V0 (2*64*KSTR)         // 9216
#define OFF_V1 (3*64*KSTR)         // 13824
#define OFF_P  (4*64*KSTR)         // 18432  (Q stage / fp32 out stage)
#define SMH    (OFF_P + 128*KSTR)  // 27648 halves = 55296 B
#define OSTR   132

__device__ __forceinline__ void stage_kv_async(uint32_t sb, const __half* Kg, const __half* Vg,
                                               int n0, int kOff, int vOff, int tid)
{
    #pragma unroll
    for (int it = 0; it < 2; it++) {
        int i = tid + it*256, r = i >> 3, c8 = (i & 7) * 8;
        CP16(sb + (uint32_t)(kOff + r*KSTR + c8)*2u, Kg + (size_t)(n0 + r)*HD + c8);
        CP16(sb + (uint32_t)(vOff + r*KSTR + c8)*2u, Vg + (size_t)(n0 + r)*HD + c8);
    }
}

__global__ __launch_bounds__(256, 2) void attn_mma(float* __restrict__ out)
{
    const int qt = 31 - (int)blockIdx.x;   // big tiles first
    const int h  = blockIdx.y;
    const int b  = blockIdx.z;

    extern __shared__ __align__(16) __half smh[];
    const uint32_t sbase = smem_u32(smh);

    const int tid = threadIdx.x, lane = tid & 31, w = tid >> 5;
    const int g = lane >> 2, t = lane & 3;
    const int r0 = w*16 + g;
    const int m  = lane >> 3, lr = lane & 7;

    // ldmatrix per-lane addresses (row stride 144 B)
    const uint32_t aQ  = sbase + (uint32_t)(OFF_P*2) + (uint32_t)(w*16 + (m&1)*8 + lr)*144u + (uint32_t)((m>>1)*8)*2u;
    const uint32_t aKo = (uint32_t)((m>>1)*8 + lr)*144u + (uint32_t)((m&1)*8)*2u;   // + buf base
    const uint32_t aVo = (uint32_t)((m&1)*8 + lr)*144u + (uint32_t)((m>>1)*8)*2u;   // + buf base

    const size_t base  = ((size_t)(b*NH + h)) * NTOK * HD;
    const int    qbase = qt * 128;
    const __half* Kg = g_K + base;
    const __half* Vg = g_V + base;

    // stage K/V tile 0 (async) + Q (sync)
    stage_kv_async(sbase, Kg, Vg, 0, OFF_K0, OFF_V0, tid);
    CP_COMMIT();
    #pragma unroll
    for (int it = 0; it < 4; it++) {
        int i = tid + it*256, r = i >> 3, d0 = (i & 7) * 8;
        *(uint4*)&smh[OFF_P + r*KSTR + d0] =
            *(const uint4*)&g_Q[base + (size_t)(qbase + r)*HD + d0];
    }
    __syncthreads();

    uint32_t qf[4][4];
    #pragma unroll
    for (int kc = 0; kc < 4; kc++) LDSM4(qf[kc], aQ + (uint32_t)(kc*16)*2u);

    float acc[8][4];
    #pragma unroll
    for (int nb = 0; nb < 8; nb++)
        #pragma unroll
        for (int c = 0; c < 4; c++) acc[nb][c] = 0.f;
    float m0 = -1e30f, m1 = -1e30f, l0 = 0.f, l1 = 0.f;  // per-lane partial l

    const int ntiles = 2*qt + 2;
    for (int j = 0; j < ntiles; j++) {
        const int n0 = j * 64;
        const uint32_t kb = sbase + (uint32_t)(((j & 1) ? OFF_K1 : OFF_K0) * 2);
        const uint32_t vb = sbase + (uint32_t)(((j & 1) ? OFF_V1 : OFF_V0) * 2);

        CP_WAIT0();
        __syncthreads();
        if (j + 1 < ntiles) {
            stage_kv_async(sbase, Kg, Vg, (j+1)*64,
                           ((j+1) & 1) ? OFF_K1 : OFF_K0,
                           ((j+1) & 1) ? OFF_V1 : OFF_V0, tid);
            CP_COMMIT();
        }

        // S = Q K^T
        float s[8][4];
        #pragma unroll
        for (int nb = 0; nb < 8; nb++)
            #pragma unroll
            for (int c = 0; c < 4; c++) s[nb][c] = 0.f;
        #pragma unroll
        for (int kc = 0; kc < 4; kc++) {
            #pragma unroll
            for (int nbp = 0; nbp < 4; nbp++) {
                uint32_t kf[4];
                LDSM4(kf, kb + aKo + (uint32_t)(nbp*16)*144u + (uint32_t)(kc*16)*2u);
                mma16(s[2*nbp  ], qf[kc], kf[0], kf[1]);
                mma16(s[2*nbp+1], qf[kc], kf[2], kf[3]);
            }
        }

        if (j >= 2*qt) {   // diagonal tiles: causal mask
            const int row = qbase + r0;
            #pragma unroll
            for (int nb = 0; nb < 8; nb++) {
                int col = n0 + nb*8 + 2*t;
                if (col     > row  ) s[nb][0] = -1e30f;
                if (col + 1 > row  ) s[nb][1] = -1e30f;
                if (col     > row+8) s[nb][2] = -1e30f;
                if (col + 1 > row+8) s[nb][3] = -1e30f;
            }
        }

        // lazy online softmax (base-2 domain)
        float mx0 = -1e30f, mx1 = -1e30f;
        #pragma unroll
        for (int nb = 0; nb < 8; nb++) {
            mx0 = fmaxf(mx0, fmaxf(s[nb][0], s[nb][1]));
            mx1 = fmaxf(mx1, fmaxf(s[nb][2], s[nb][3]));
        }
        if (__any_sync(0xffffffffu, (mx0 > m0) | (mx1 > m1))) {
            mx0 = fmaxf(mx0, __shfl_xor_sync(0xffffffffu, mx0, 1));
            mx0 = fmaxf(mx0, __shfl_xor_sync(0xffffffffu, mx0, 2));
            mx1 = fmaxf(mx1, __shfl_xor_sync(0xffffffffu, mx1, 1));
            mx1 = fmaxf(mx1, __shfl_xor_sync(0xffffffffu, mx1, 2));
            float mn0 = fmaxf(m0, mx0), mn1 = fmaxf(m1, mx1);
            float sc0 = ex2f(m0 - mn0), sc1 = ex2f(m1 - mn1);
            l0 *= sc0;  l1 *= sc1;
            #pragma unroll
            for (int nb = 0; nb < 8; nb++) {
                acc[nb][0] *= sc0; acc[nb][1] *= sc0;
                acc[nb][2] *= sc1; acc[nb][3] *= sc1;
            }
            m0 = mn0;  m1 = mn1;
        }

        // p = 2^(s-m); P A-fragments built directly in registers
        uint32_t pa[4][4];
        #pragma unroll
        for (int kc = 0; kc < 4; kc++) {
            float p00 = ex2f(s[2*kc  ][0]-m0), p01 = ex2f(s[2*kc  ][1]-m0);
            float p02 = ex2f(s[2*kc  ][2]-m1), p03 = ex2f(s[2*kc  ][3]-m1);
            float p10 = ex2f(s[2*kc+1][0]-m0), p11 = ex2f(s[2*kc+1][1]-m0);
            float p12 = ex2f(s[2*kc+1][2]-m1), p13 = ex2f(s[2*kc+1][3]-m1);
            l0 += p00 + p01 + p10 + p11;
            l1 += p02 + p03 + p12 + p13;
            pa[kc][0] = pack2(p00, p01);
            pa[kc][1] = pack2(p02, p03);
            pa[kc][2] = pack2(p10, p11);
            pa[kc][3] = pack2(p12, p13);
        }

        // O += P V  (A from registers, B = V via ldmatrix.trans)
        #pragma unroll
        for (int kc = 0; kc < 4; kc++) {
            #pragma unroll
            for (int nbp = 0; nbp < 4; nbp++) {
                uint32_t vf[4];
                LDSM4T(vf, vb + aVo + (uint32_t)(kc*16)*144u + (uint32_t)(nbp*16)*2u);
                mma16(acc[2*nbp  ], pa[kc], vf[0], vf[1]);
                mma16(acc[2*nbp+1], pa[kc], vf[2], vf[3]);
            }
        }
    }

    // epilogue: reduce l across the quad, /l, transposed coalesced store
    l0 += __shfl_xor_sync(0xffffffffu, l0, 1);
    l0 += __shfl_xor_sync(0xffffffffu, l0, 2);
    l1 += __shfl_xor_sync(0xffffffffu, l1, 1);
    l1 += __shfl_xor_sync(0xffffffffu, l1, 2);
    float inv0 = 1.f / l0, inv1 = 1.f / l1;
    #pragma unroll
    for (int nb = 0; nb < 8; nb++) {
        acc[nb][0] *= inv0; acc[nb][1] *= inv0;
        acc[nb][2] *= inv1; acc[nb][3] *= inv1;
    }
    __syncthreads();
    float* Osm = (float*)smh;
    #pragma unroll
    for (int nb = 0; nb < 8; nb++) {
        int d = nb*8 + 2*t;
        Osm[(d  )*OSTR + r0    ] = acc[nb][0];
        Osm[(d+1)*OSTR + r0    ] = acc[nb][1];
        Osm[(d  )*OSTR + r0 + 8] = acc[nb][2];
        Osm[(d+1)*OSTR + r0 + 8] = acc[nb][3];
    }
    __syncthreads();
    const size_t obase = ((size_t)b*EMB + h*HD) * NTOK + qbase;
    for (int i = tid; i < 64*128; i += 256) {
        int d = i >> 7, n = i & 127;
        out[obase + (size_t)d * NTOK + n] = Osm[d*OSTR + n];
    }
}

// ---------------------------------------------------------------------------
extern "C" void kernel_launch(void* const* d_in, const int* in_sizes, int n_in,
                              void* d_out, int out_size)
{
    const float* query = (const float*)d_in[0];
    const float* key   = (const float*)d_in[1];
    const float* Wq    = (const float*)d_in[2];
    const float* bq    = (const float*)d_in[3];
    const float* Wk    = (const float*)d_in[4];
    const float* bk    = (const float*)d_in[5];
    const float* Wv    = (const float*)d_in[6];
    const float* bv    = (const float*)d_in[7];
    float* out = (float*)d_out;

    dim3 pgrid(64, 4, 3);
    proj_mma<<<pgrid, 256>>>(query, key, Wq, bq, Wk, bk, Wv, bv);

    const int attn_smem = SMH * (int)sizeof(__half);   // 55,296 B
    cudaFuncSetAttribute(attn_mma,
                         cudaFuncAttributeMaxDynamicSharedMemorySize, attn_smem);
    dim3 agrid(32, NH, 2);
    attn_mma<<<agrid, 256, attn_smem>>>(out);
}